// round 10
// baseline (speedup 1.0000x reference)
#include <cuda_runtime.h>
#include <cuda_fp16.h>
#include <cstdint>

#define BB 4
#define LL 1024
#define VV 50257
#define DD 512

// ---- scratch (no allocations allowed) ----
__device__ float  g_xproj[BB * LL * DD];          // [b*L+t][D] fp32
__device__ __half g_hs_h[BB * LL * DD];           // [b*L+t][D] fp16 (K3 A operand)
__device__ __half g_wo_h[(size_t)VV * DD];        // Wo as fp16

// =====================================================================
// helpers (base sm_103 ISA only — no 'a'-suffix features)
// =====================================================================
__device__ __forceinline__ uint32_t smem_u32(const void* p)
{
    uint32_t a;
    asm("{ .reg .u64 t; cvta.to.shared.u64 t, %1; cvt.u32.u64 %0, t; }" : "=r"(a) : "l"(p));
    return a;
}
#define SWZ128(x) ((x) ^ (((x) >> 3) & 0x70))

__device__ __forceinline__ void cpa16(uint32_t dst, const void* src, bool valid)
{
    asm volatile("cp.async.cg.shared.global [%0], [%1], 16, %2;"
                 :: "r"(dst), "l"(src), "r"(valid ? 16 : 0));
}
__device__ __forceinline__ void cpa_commit() { asm volatile("cp.async.commit_group;"); }
template <int N> __device__ __forceinline__ void cpa_wait() { asm volatile("cp.async.wait_group %0;" :: "n"(N)); }

__device__ __forceinline__ void ldm4(uint32_t* r, uint32_t addr)
{
    asm volatile("ldmatrix.sync.aligned.m8n8.x4.shared.b16 {%0,%1,%2,%3}, [%4];"
                 : "=r"(r[0]), "=r"(r[1]), "=r"(r[2]), "=r"(r[3]) : "r"(addr));
}
__device__ __forceinline__ void mma16816(float* c, const uint32_t* a, uint32_t b0, uint32_t b1)
{
    asm volatile("mma.sync.aligned.m16n8k16.row.col.f32.f16.f16.f32 "
                 "{%0,%1,%2,%3}, {%4,%5,%6,%7}, {%8,%9}, {%0,%1,%2,%3};"
                 : "+f"(c[0]), "+f"(c[1]), "+f"(c[2]), "+f"(c[3])
                 : "r"(a[0]), "r"(a[1]), "r"(a[2]), "r"(a[3]), "r"(b0), "r"(b1));
}
__device__ __forceinline__ void st_cluster_f32(uint32_t laddr, uint32_t rank, float v)
{
    uint32_t ra;
    asm volatile("mapa.shared::cluster.u32 %0, %1, %2;" : "=r"(ra) : "r"(laddr), "r"(rank));
    asm volatile("st.shared::cluster.f32 [%0], %1;" :: "r"(ra), "f"(v) : "memory");
}
#define CL_ARRIVE() asm volatile("barrier.cluster.arrive.aligned;" ::: "memory")
#define CL_WAIT()   asm volatile("barrier.cluster.wait.aligned;" ::: "memory")

// packed f32x2 (base sm_103 ISA; proven in round 1)
__device__ __forceinline__ unsigned long long pk2(float lo, float hi)
{
    unsigned long long r;
    asm("mov.b64 %0, {%1, %2};" : "=l"(r) : "f"(lo), "f"(hi));
    return r;
}
__device__ __forceinline__ void fma2(unsigned long long& d, unsigned long long a, unsigned long long b)
{
    asm("fma.rn.f32x2 %0, %1, %2, %0;" : "+l"(d) : "l"(a), "l"(b));
}
__device__ __forceinline__ float2 upk2(unsigned long long v)
{
    float2 r;
    asm("mov.b64 {%0, %1}, %2;" : "=f"(r.x), "=f"(r.y) : "l"(v));
    return r;
}

// =====================================================================
// K0: Wo fp32 -> fp16
// =====================================================================
__global__ void k0_conv(const float* __restrict__ Wo)
{
    const size_t i4 = (size_t)blockIdx.x * blockDim.x + threadIdx.x;
    if (i4 * 4 >= (size_t)VV * DD) return;
    float4 v = *(const float4*)(Wo + i4 * 4);
    __half2* dst = (__half2*)(g_wo_h + i4 * 4);
    dst[0] = __floats2half2_rn(v.x, v.y);
    dst[1] = __floats2half2_rn(v.z, v.w);
}

// =====================================================================
// K1: xproj = emb[tok] @ Wx^T + bx   (M=4096, N=512, K=512)
// =====================================================================
__global__ void k1_xproj(const int* __restrict__ tok, const float* __restrict__ emb,
                         const float* __restrict__ Wx, const float* __restrict__ bx)
{
    __shared__ float As[16][64];
    __shared__ float Bs[16][64];
    __shared__ int toks[64];
    const int m0 = blockIdx.y * 64;
    const int n0 = blockIdx.x * 64;
    const int tid = threadIdx.x;
    if (tid < 64) toks[tid] = tok[m0 + tid];
    __syncthreads();
    const int tm = tid >> 4, tn = tid & 15;
    const int lr = tid >> 2;
    const int lk = (tid & 3) << 2;
    const float* arow = emb + (size_t)toks[lr] * DD + lk;
    const float* brow = Wx + (size_t)(n0 + lr) * DD + lk;
    float acc[4][4] = {};
    for (int k0 = 0; k0 < DD; k0 += 16) {
        float4 av = *(const float4*)(arow + k0);
        float4 bv = *(const float4*)(brow + k0);
        __syncthreads();
        As[lk + 0][lr] = av.x; As[lk + 1][lr] = av.y;
        As[lk + 2][lr] = av.z; As[lk + 3][lr] = av.w;
        Bs[lk + 0][lr] = bv.x; Bs[lk + 1][lr] = bv.y;
        Bs[lk + 2][lr] = bv.z; Bs[lk + 3][lr] = bv.w;
        __syncthreads();
        #pragma unroll
        for (int k = 0; k < 16; k++) {
            float a[4], b[4];
            *(float4*)a = *(const float4*)&As[k][tm * 4];
            *(float4*)b = *(const float4*)&Bs[k][tn * 4];
            #pragma unroll
            for (int i = 0; i < 4; i++)
                #pragma unroll
                for (int j = 0; j < 4; j++)
                    acc[i][j] = fmaf(a[i], b[j], acc[i][j]);
        }
    }
    #pragma unroll
    for (int i = 0; i < 4; i++) {
        const int m = m0 + tm * 4 + i;
        #pragma unroll
        for (int j = 0; j < 4; j++) {
            const int e = n0 + tn * 4 + j;
            g_xproj[(size_t)m * DD + e] = acc[i][j] + bx[e];
        }
    }
}

// =====================================================================
// K2: recurrence, 8-CTA cluster per batch (4 clusters), split cluster
// barrier + xproj prefetch (round-6 skeleton), now issue-optimized:
//  - lane owns 16 CONTIGUOUS-by-4 d's: d = 4*lane + 128*j (j=0..3)
//    -> h loads are 4x LDS.128, conflict-free (16B lane stride)
//  - weights pre-packed as f32x2; inner product = 32 fma.rn.f32x2
//    (vs 64 FFMA + 16 scalar LDS before): ~2x fewer issue slots
// =====================================================================
__global__ __launch_bounds__(512, 1) __cluster_dims__(8, 1, 1)
void k2_recur(const float* __restrict__ Wh, const float* __restrict__ bh)
{
    __shared__ float sh[2][DD];
    const int tid = threadIdx.x;
    const int lane = tid & 31;
    const int w = tid >> 5;                 // 0..15
    const int batch = blockIdx.x >> 3;
    const int crank = blockIdx.x & 7;
    const int e_base = crank * 64 + w * 4;  // this warp's 4 e's

    // packed weights: wp[e][j*2+p] = (Wh[e][4l+128j+2p], Wh[e][4l+128j+2p+1])
    unsigned long long wp[4][8];
    float bias[4];
    #pragma unroll
    for (int j = 0; j < 4; j++) {
        bias[j] = bh[e_base + j];
        #pragma unroll
        for (int q = 0; q < 4; q++) {
            float4 wv = *(const float4*)(Wh + (size_t)(e_base + j) * DD + 4 * lane + 128 * q);
            wp[j][2 * q]     = pk2(wv.x, wv.y);
            wp[j][2 * q + 1] = pk2(wv.z, wv.w);
        }
    }
    const float* xp = g_xproj + (size_t)batch * LL * DD;

    // t = 0: h_prev = 0
    {
        float v[4];
        #pragma unroll
        for (int j = 0; j < 4; j++)
            v[j] = fmaxf(bias[j] + __ldcg(xp + e_base + j), 0.f);
        if (lane < 8) {
            #pragma unroll
            for (int j = 0; j < 4; j++)
                st_cluster_f32(smem_u32(&sh[0][e_base + j]), lane, v[j]);
        }
        if (lane == 8) {
            __half2* dst = (__half2*)(g_hs_h + (size_t)(batch * LL) * DD + e_base);
            dst[0] = __floats2half2_rn(v[0], v[1]);
            dst[1] = __floats2half2_rn(v[2], v[3]);
        }
    }
    CL_ARRIVE();

    // prefetch xv for t = 1
    float xv_n[4];
    #pragma unroll
    for (int j = 0; j < 4; j++)
        xv_n[j] = __ldcg(xp + (size_t)1 * DD + e_base + j);

    for (int t = 1; t < LL; t++) {
        CL_WAIT();                      // h_{t-1} stores now visible

        float xv[4];
        #pragma unroll
        for (int j = 0; j < 4; j++) xv[j] = xv_n[j];

        // prefetch next step's xproj FIRST (LDG leaves before LDS chain)
        if (t + 1 < LL) {
            #pragma unroll
            for (int j = 0; j < 4; j++)
                xv_n[j] = __ldcg(xp + (size_t)(t + 1) * DD + e_base + j);
        }

        // h: 4x LDS.128, pack to f32x2
        const float* hb = sh[(t - 1) & 1];
        unsigned long long hp[8];
        #pragma unroll
        for (int q = 0; q < 4; q++) {
            float4 hv = *(const float4*)(hb + 4 * lane + 128 * q);
            hp[2 * q]     = pk2(hv.x, hv.y);
            hp[2 * q + 1] = pk2(hv.z, hv.w);
        }

        // 4 dots via packed FMA (32 f32x2 ops)
        float acc[4];
        #pragma unroll
        for (int j = 0; j < 4; j++) {
            unsigned long long a2 = 0ull;
            #pragma unroll
            for (int q = 0; q < 8; q++)
                fma2(a2, wp[j][q], hp[q]);
            float2 h2 = upk2(a2);
            acc[j] = h2.x + h2.y;
        }

        #pragma unroll
        for (int off = 16; off > 0; off >>= 1)
            #pragma unroll
            for (int j = 0; j < 4; j++)
                acc[j] += __shfl_xor_sync(0xffffffffu, acc[j], off);

        float v[4];
        #pragma unroll
        for (int j = 0; j < 4; j++)
            v[j] = fmaxf(acc[j] + bias[j] + xv[j], 0.f);

        if (t < LL - 1) {
            if (lane < 8) {
                #pragma unroll
                for (int j = 0; j < 4; j++)
                    st_cluster_f32(smem_u32(&sh[t & 1][e_base + j]), lane, v[j]);
            }
            CL_ARRIVE();
        }
        if (lane == 8) {
            __half2* dst = (__half2*)(g_hs_h + (size_t)(batch * LL + t) * DD + e_base);
            dst[0] = __floats2half2_rn(v[0], v[1]);
            dst[1] = __floats2half2_rn(v[2], v[3]);
        }
    }
}

// =====================================================================
// K3: out = hs @ Wo^T + bo  (M=4096, N=50257, K=512) — fp16 HMMA.
// CTA 128x128, warp tile 64x32 (2m x 4n), BK=64, 3-stage cp.async,
// 2 CTAs/SM, single sync per chunk (no trailing sync: issue(c+2)
// targets stage (c-1)%3 whose reads finished before the top sync).
// bo tile in smem. VV odd => scalar fp32 stores. (measured 681us)
// =====================================================================
#define K3_BM 128
#define K3_BN 128
#define K3_BKH 64
#define K3_NCH (DD / K3_BKH)                     // 8
#define K3_STAGE_BYTES ((K3_BM + K3_BN) * 128)   // 32768
#define K3_STAGES 3
#define K3_SMEM_BYTES (K3_STAGES * K3_STAGE_BYTES + K3_BN * 4)  // 98816

__global__ __launch_bounds__(256, 2)
void k3_mma(const float* __restrict__ bo, float* __restrict__ out)
{
    extern __shared__ __align__(1024) char smc[];
    const uint32_t smem_base = smem_u32(smc);
    float* bo_s = (float*)(smc + K3_STAGES * K3_STAGE_BYTES);
    const int tid = threadIdx.x;
    const int wid = tid >> 5;
    const int lane = tid & 31;
    const int m0 = blockIdx.x * K3_BM;
    const int n0 = blockIdx.y * K3_BN;
    const int warp_m = (wid & 1) * 64;
    const int warp_n = (wid >> 1) * 32;

    if (tid < K3_BN) {
        const int v = n0 + tid;
        bo_s[tid] = (v < VV) ? bo[v] : 0.f;
    }

    // ---- loader: 16B segs, swizzled 128B rows
    const int seg = tid & 7;
    const int r0 = tid >> 3;      // 0..31
    auto issue = [&](int c, int s) {
        const uint32_t abase = smem_base + s * K3_STAGE_BYTES;
        const uint32_t bbase = abase + K3_BM * 128;
        const __half* asrc = g_hs_h + (size_t)(m0 + r0) * DD + c * K3_BKH + seg * 8;
        #pragma unroll
        for (int i = 0; i < 4; i++) {
            const int row = r0 + 32 * i;
            cpa16(abase + SWZ128(row * 128 + seg * 16), asrc + (size_t)32 * i * DD, true);
        }
        #pragma unroll
        for (int i = 0; i < 4; i++) {
            const int row = r0 + 32 * i;
            const int v = n0 + row;
            const __half* bsrc = g_wo_h + (size_t)(v < VV ? v : 0) * DD + c * K3_BKH + seg * 8;
            cpa16(bbase + SWZ128(row * 128 + seg * 16), bsrc, v < VV);
        }
        cpa_commit();
    };

    issue(0, 0);
    issue(1, 1);

    // ldmatrix lane geometry
    int arow[4], axor[4];
    #pragma unroll
    for (int f = 0; f < 4; f++) {
        const int row = warp_m + f * 16 + (lane & 15);
        arow[f] = row * 128;
        axor[f] = (row & 7) * 16;
    }
    const int acol0 = (lane >> 4) * 16;
    int brow[2], bxor[2];
    #pragma unroll
    for (int g = 0; g < 2; g++) {
        const int nr = warp_n + g * 16 + ((lane & 16) >> 1) + (lane & 7);
        brow[g] = nr * 128;
        bxor[g] = (nr & 7) * 16;
    }
    const int bcol0 = ((lane >> 3) & 1) * 16;

    float acc[4][4][4];
    #pragma unroll
    for (int i = 0; i < 4; i++)
        #pragma unroll
        for (int j = 0; j < 4; j++)
            #pragma unroll
            for (int q = 0; q < 4; q++) acc[i][j][q] = 0.f;

    for (int c = 0; c < K3_NCH; c++) {
        if (c == K3_NCH - 1) cpa_wait<0>(); else cpa_wait<1>();
        __syncthreads();
        if (c + 2 < K3_NCH) issue(c + 2, (c + 2) % K3_STAGES);

        const uint32_t Ast = smem_base + (c % K3_STAGES) * K3_STAGE_BYTES;
        const uint32_t Bst = Ast + K3_BM * 128;

        #pragma unroll
        for (int ks = 0; ks < 4; ks++) {
            uint32_t A[4][4];
            #pragma unroll
            for (int f = 0; f < 4; f++)
                ldm4(A[f], Ast + arow[f] + ((acol0 + 32 * ks) ^ axor[f]));
            uint32_t Bf[2][4];
            #pragma unroll
            for (int g = 0; g < 2; g++)
                ldm4(Bf[g], Bst + brow[g] + ((bcol0 + 32 * ks) ^ bxor[g]));
            #pragma unroll
            for (int fm = 0; fm < 4; fm++)
                #pragma unroll
                for (int g = 0; g < 2; g++) {
                    mma16816(acc[fm][2 * g],     A[fm], Bf[g][0], Bf[g][1]);
                    mma16816(acc[fm][2 * g + 1], A[fm], Bf[g][2], Bf[g][3]);
                }
        }
        // no trailing sync (see header comment)
    }

    // ---- epilogue: scalar 32-bit stores (VV odd => rows only 4B-aligned)
    #pragma unroll
    for (int fm = 0; fm < 4; fm++) {
        const int m = m0 + warp_m + fm * 16 + (lane >> 2);
        float* orow0 = out + (size_t)m * VV;
        float* orow1 = out + (size_t)(m + 8) * VV;
        #pragma unroll
        for (int fn = 0; fn < 4; fn++) {
            const int nloc = warp_n + fn * 8 + 2 * (lane & 3);
            const int v = n0 + nloc;
            if (v < VV) {
                const float b0 = bo_s[nloc];
                orow0[v] = acc[fm][fn][0] + b0;
                orow1[v] = acc[fm][fn][2] + b0;
            }
            if (v + 1 < VV) {
                const float b1 = bo_s[nloc + 1];
                orow0[v + 1] = acc[fm][fn][1] + b1;
                orow1[v + 1] = acc[fm][fn][3] + b1;
            }
        }
    }
}

// =====================================================================
extern "C" void kernel_launch(void* const* d_in, const int* in_sizes, int n_in,
                              void* d_out, int out_size)
{
    const int*   tok = (const int*)d_in[0];
    const float* emb = (const float*)d_in[1];
    const float* Wh  = (const float*)d_in[2];
    const float* bh  = (const float*)d_in[3];
    const float* Wx  = (const float*)d_in[4];
    const float* bx  = (const float*)d_in[5];
    const float* Wo  = (const float*)d_in[6];
    const float* bo  = (const float*)d_in[7];
    float* out = (float*)d_out;

    const size_t n4 = ((size_t)VV * DD) / 4;
    k0_conv<<<(unsigned)((n4 + 255) / 256), 256>>>(Wo);

    dim3 g1(DD / 64, (BB * LL) / 64);
    k1_xproj<<<g1, 256>>>(tok, emb, Wx, bx);

    k2_recur<<<32, 512>>>(Wh, bh);   // 4 clusters of 8 CTAs

    cudaFuncSetAttribute(k3_mma, cudaFuncAttributeMaxDynamicSharedMemorySize, K3_SMEM_BYTES);
    dim3 g3((BB * LL) / K3_BM, (VV + K3_BN - 1) / K3_BN);   // (32, 393), M fastest
    k3_mma<<<g3, 256, K3_SMEM_BYTES>>>(bo, out);
}